// round 15
// baseline (speedup 1.0000x reference)
#include <cuda_runtime.h>
#include <cuda_bf16.h>
#include <cstdint>
#include <cstddef>

typedef __nv_bfloat16 bf16;

#define BB   1024
#define CIN  256
#define HH   512
#define TT   32
#define EE   512
#define NEC  8192
#define RECON_N (BB*CIN*TT)
#define NNC  (BB*TT)          // 32768 GEMM-N for convs

// BK=64 tiles: 4 tiles x 128 rows x 144B (64 bf16 + 16B pad) = 73728/buf
#define TSTRIDE 144
#define TILEB   18432
#define BUFB    73728
#define GS      147456        // 2 buffers

// ---------------- static device scratch ----------------
__device__ bf16 g_actAh[(size_t)NNC*HH], g_actAl[(size_t)NNC*HH];
__device__ bf16 g_actBh[(size_t)NNC*HH], g_actBl[(size_t)NNC*HH];
__device__ bf16 g_wA1h[512*768],   g_wA1l[512*768];
__device__ bf16 g_wA2h[512*1536],  g_wA2l[512*1536];
__device__ bf16 g_wA3h[512*1536],  g_wA3l[512*1536];
__device__ bf16 g_wA4h[512*1536],  g_wA4l[512*1536];
__device__ bf16 g_wD4h[512*1536],  g_wD4l[512*1536];
__device__ bf16 g_wD3h[512*1536],  g_wD3l[512*1536];
__device__ bf16 g_wD2h[512*1536],  g_wD2l[512*1536];
__device__ bf16 g_wD1h[256*1536],  g_wD1l[256*1536];
__device__ bf16 g_wFEh[(size_t)512*16384], g_wFEl[(size_t)512*16384];
__device__ bf16 g_wFDh[(size_t)16384*512], g_wFDl[(size_t)16384*512];
__device__ bf16 g_cbh[(size_t)NEC*EE],     g_cbl[(size_t)NEC*EE];
__device__ float g_dfb2[16384];
__device__ float g_part[(size_t)8*BB*EE];
__device__ float g_z[(size_t)BB*EE];
__device__ bf16  g_zh[(size_t)BB*EE],  g_zl[(size_t)BB*EE];
__device__ bf16  g_zqh[(size_t)BB*EE], g_zql[(size_t)BB*EE];
__device__ float g_dot[(size_t)BB*NEC];
__device__ float g_cn[NEC];
__device__ float g_lp[BB];

// ---------------- helpers ----------------
__device__ __forceinline__ void split2(float v, bf16& h, bf16& l){
    h = __float2bfloat16_rn(v);
    l = __float2bfloat16_rn(v - __bfloat162float(h));
}
__device__ __forceinline__ void mma_bf16(float* c, const uint32_t* a, const uint32_t* b){
    asm volatile("mma.sync.aligned.m16n8k16.row.col.f32.bf16.bf16.f32 "
        "{%0,%1,%2,%3}, {%4,%5,%6,%7}, {%8,%9}, {%0,%1,%2,%3};"
        : "+f"(c[0]), "+f"(c[1]), "+f"(c[2]), "+f"(c[3])
        : "r"(a[0]), "r"(a[1]), "r"(a[2]), "r"(a[3]), "r"(b[0]), "r"(b[1]));
}
template<int N> __device__ __forceinline__ void cp_wait(){
    asm volatile("cp.async.wait_group %0;" :: "n"(N) : "memory");
}
__device__ __forceinline__ void cp_commit(){
    asm volatile("cp.async.commit_group;" ::: "memory");
}

// stage one 128x64 x4-tile chunk into buffer `buf` (16B cp.async, zfill halo)
__device__ __forceinline__ void stage_chunk(
    uint32_t sbU, int buf,
    const bf16* __restrict__ Ah, const bf16* __restrict__ Al,
    const bf16* __restrict__ Bh, const bf16* __restrict__ Bl,
    int m0, int n0, int k0, int K, int convC, int tid)
{
    uint32_t sb = sbU + buf*BUFB;
    // A tiles: 128 rows x 8 segs of 16B, hi then lo
    #pragma unroll
    for (int half = 0; half < 2; half++){
        const bf16* src = half ? Al : Ah;
        uint32_t tb = sb + half*TILEB;
        #pragma unroll
        for (int it = 0; it < 4; it++){
            int task = tid + it*256;            // 1024 tasks
            int r = task >> 3, seg = task & 7;
            const void* g = src + (size_t)(m0 + r)*K + k0 + seg*8;
            asm volatile("cp.async.cg.shared.global [%0], [%1], 16;"
                :: "r"(tb + r*TSTRIDE + seg*16), "l"(g));
        }
    }
    // B tiles
    #pragma unroll
    for (int half = 0; half < 2; half++){
        const bf16* src = half ? Bl : Bh;
        uint32_t tb = sb + 2*TILEB + half*TILEB;
        #pragma unroll
        for (int it = 0; it < 4; it++){
            int task = tid + it*256;
            int r = task >> 3, seg = task & 7;
            int n = n0 + r;
            const bf16* g; int sz = 16;
            if (convC){
                int t = n & 31, ks2 = k0 / convC, kr = k0 - ks2*convC;
                if ((unsigned)(t + ks2 - 1) < 32u)
                    g = src + (size_t)(n + ks2 - 1)*convC + kr + seg*8;
                else { g = src; sz = 0; }
            } else {
                g = src + (size_t)n*K + k0 + seg*8;
            }
            asm volatile("cp.async.cg.shared.global [%0], [%1], 16, %2;"
                :: "r"(tb + r*TSTRIDE + seg*16), "l"((const void*)g), "r"(sz));
        }
    }
}

// =====================================================================
// split-bf16 NT GEMM via mma.sync, BK=64 double-buffered (R4 numerics).
// grid = (Ntot/128, Mtot/128, zsplit). convC: implicit im2col on B rows.
// fmode 1 -> outF[n*ldc+m]; fmode 2 -> outF[(n>>5)*Mtot*32+m*32+(n&31)];
// outH/outL -> split act at [n*Mtot+m]. zsplit>1: fp32 partials.
// =====================================================================
__global__ void __launch_bounds__(256) gemm_mma(
    const bf16* __restrict__ Ah, const bf16* __restrict__ Al,
    const bf16* __restrict__ Bh, const bf16* __restrict__ Bl,
    const float* __restrict__ bias, float* __restrict__ outF,
    bf16* __restrict__ outH, bf16* __restrict__ outL,
    float* __restrict__ partBase,
    int Mtot, int K, int kseg, int convC, int fmode, int ldc, int relu)
{
    extern __shared__ char smem[];
    const uint32_t sbU = (uint32_t)__cvta_generic_to_shared(smem);
    const int tid  = threadIdx.x;
    const int lane = tid & 31, wid = tid >> 5;
    const int wm = wid >> 2, wn = wid & 3;     // 2 x 4 warps, 64x32 each
    const int m0 = blockIdx.y * 128;
    const int n0 = blockIdx.x * 128;
    const int kb = blockIdx.z * kseg;
    const int NC = kseg / 64;

    float acc[4][4][4];
    #pragma unroll
    for (int i = 0; i < 4; i++)
        #pragma unroll
        for (int j = 0; j < 4; j++)
            #pragma unroll
            for (int r = 0; r < 4; r++) acc[i][j][r] = 0.f;

    stage_chunk(sbU, 0, Ah, Al, Bh, Bl, m0, n0, kb, K, convC, tid);
    cp_commit();
    if (NC > 1){
        stage_chunk(sbU, 1, Ah, Al, Bh, Bl, m0, n0, kb + 64, K, convC, tid);
        cp_commit();
    }

    const uint32_t* sw = (const uint32_t*)smem;

    for (int ci = 0; ci < NC; ci++){
        if (ci + 1 < NC) cp_wait<1>(); else cp_wait<0>();
        __syncthreads();

        const uint32_t* sb  = sw + (ci & 1) * (BUFB/4);
        const uint32_t* sAh = sb;
        const uint32_t* sAl = sb + TILEB/4;
        const uint32_t* sBh = sb + 2*(TILEB/4);
        const uint32_t* sBl = sb + 3*(TILEB/4);

        #pragma unroll
        for (int s = 0; s < 4; s++){
            const int kwo = s*8;     // k16 step in u32 words
            uint32_t ah[4][4], al[4][4], bh[4][2], bl[4][2];
            #pragma unroll
            for (int i = 0; i < 4; i++){
                int wb = (wm*64 + i*16 + (lane >> 2))*36 + kwo + (lane & 3);
                ah[i][0] = sAh[wb];       ah[i][1] = sAh[wb + 288];
                ah[i][2] = sAh[wb + 4];   ah[i][3] = sAh[wb + 292];
                al[i][0] = sAl[wb];       al[i][1] = sAl[wb + 288];
                al[i][2] = sAl[wb + 4];   al[i][3] = sAl[wb + 292];
            }
            #pragma unroll
            for (int j = 0; j < 4; j++){
                int wb = (wn*32 + j*8 + (lane >> 2))*36 + kwo + (lane & 3);
                bh[j][0] = sBh[wb];  bh[j][1] = sBh[wb + 4];
                bl[j][0] = sBl[wb];  bl[j][1] = sBl[wb + 4];
            }
            #pragma unroll
            for (int i = 0; i < 4; i++)
                #pragma unroll
                for (int j = 0; j < 4; j++){
                    mma_bf16(acc[i][j], ah[i], bh[j]);
                    mma_bf16(acc[i][j], ah[i], bl[j]);
                    mma_bf16(acc[i][j], al[i], bh[j]);
                }
        }
        __syncthreads();
        if (ci + 2 < NC){
            stage_chunk(sbU, ci & 1, Ah, Al, Bh, Bl, m0, n0,
                        kb + (ci + 2)*64, K, convC, tid);
            cp_commit();
        }
    }

    // ---- epilogue ----
    const bool dosplit = (gridDim.z > 1);
    const int nTot = gridDim.x * 128;
    float* fO = outF; int fm = fmode; int lld = ldc;
    bf16 *oH = outH, *oL = outL;
    if (dosplit){
        fO = partBase + (size_t)blockIdx.z * Mtot * nTot;
        fm = 1; lld = Mtot; oH = nullptr; oL = nullptr;
    }
    #pragma unroll
    for (int i = 0; i < 4; i++){
        const int mA = m0 + wm*64 + i*16 + (lane >> 2);
        const int mB = mA + 8;
        const float bvA = (!dosplit && bias) ? bias[mA] : 0.f;
        const float bvB = (!dosplit && bias) ? bias[mB] : 0.f;
        #pragma unroll
        for (int j = 0; j < 4; j++){
            const int nb = n0 + wn*32 + j*8 + (lane & 3)*2;
            float v[4];
            v[0] = acc[i][j][0] + bvA;  v[1] = acc[i][j][1] + bvA;
            v[2] = acc[i][j][2] + bvB;  v[3] = acc[i][j][3] + bvB;
            if (relu){
                #pragma unroll
                for (int r = 0; r < 4; r++) v[r] = fmaxf(v[r], 0.f);
            }
            const int mm[4] = {mA, mA, mB, mB};
            const int nn[4] = {nb, nb + 1, nb, nb + 1};
            #pragma unroll
            for (int r = 0; r < 4; r++){
                const int m = mm[r], n = nn[r];
                if (fm == 1)
                    fO[(size_t)n * lld + m] = v[r];
                else if (fm == 2)
                    fO[(size_t)(n >> 5) * ((size_t)Mtot * 32) + (size_t)m * 32 + (n & 31)] = v[r];
                if (oH){
                    bf16 h = __float2bfloat16_rn(v[r]);
                    oH[(size_t)n * Mtot + m] = h;
                    oL[(size_t)n * Mtot + m] = __float2bfloat16_rn(v[r] - __bfloat162float(h));
                }
            }
        }
    }
}

// ---------------- transforms ----------------
__global__ __launch_bounds__(256) void wconv_k(const float* __restrict__ w,
    bf16* __restrict__ h, bf16* __restrict__ l, int O, int C, int isT)
{
    int total = O * C * 3;
    for (int i = blockIdx.x*blockDim.x + threadIdx.x; i < total; i += gridDim.x*blockDim.x){
        int o = i / (C*3), r = i % (C*3), c = r / 3, k = r % 3;
        float v = isT ? w[((size_t)c*O + o)*3 + (2 - k)] : w[i];
        size_t d = (size_t)o*(3*C) + k*C + c;
        bf16 hh, ll; split2(v, hh, ll); h[d] = hh; l[d] = ll;
    }
}
__global__ __launch_bounds__(256) void wfe_k(const float* __restrict__ w,
    bf16* __restrict__ h, bf16* __restrict__ l)
{
    size_t total = (size_t)512*16384;
    for (size_t i = blockIdx.x*(size_t)blockDim.x + threadIdx.x; i < total;
         i += (size_t)gridDim.x*blockDim.x){
        int e = (int)(i >> 14), fp = (int)(i & 16383);
        int t = fp >> 9, c = fp & 511;
        float v = w[(size_t)e*16384 + c*32 + t];
        bf16 hh, ll; split2(v, hh, ll); h[i] = hh; l[i] = ll;
    }
}
__global__ __launch_bounds__(256) void wfd_k(const float* __restrict__ w,
    bf16* __restrict__ h, bf16* __restrict__ l)
{
    size_t total = (size_t)16384*512;
    for (size_t i = blockIdx.x*(size_t)blockDim.x + threadIdx.x; i < total;
         i += (size_t)gridDim.x*blockDim.x){
        int fp = (int)(i >> 9), e = (int)(i & 511);
        int t = fp >> 9, c = fp & 511;
        float v = w[((size_t)(c*32 + t))*512 + e];
        bf16 hh, ll; split2(v, hh, ll); h[i] = hh; l[i] = ll;
    }
}
__global__ __launch_bounds__(256) void dfb2_k(const float* __restrict__ b,
    float* __restrict__ b2)
{
    int i = blockIdx.x*blockDim.x + threadIdx.x;
    int t = i >> 9, c = i & 511;
    b2[i] = b[c*32 + t];
}
__global__ __launch_bounds__(256) void plainsplit_k(const float* __restrict__ s,
    bf16* __restrict__ h, bf16* __restrict__ l, size_t n)
{
    for (size_t i = blockIdx.x*(size_t)blockDim.x + threadIdx.x; i < n;
         i += (size_t)gridDim.x*blockDim.x){
        bf16 hh, ll; split2(s[i], hh, ll); h[i] = hh; l[i] = ll;
    }
}
__global__ __launch_bounds__(256) void xsplit_k(const float* __restrict__ x,
    bf16* __restrict__ h, bf16* __restrict__ l)
{
    size_t total = (size_t)BB*CIN*TT;
    for (size_t i = blockIdx.x*(size_t)blockDim.x + threadIdx.x; i < total;
         i += (size_t)gridDim.x*blockDim.x){
        int b = (int)(i >> 13), r = (int)(i & 8191);
        int c = r >> 5, t = r & 31;
        size_t d = (size_t)(b*32 + t)*256 + c;
        bf16 hh, ll; split2(x[i], hh, ll); h[d] = hh; l[d] = ll;
    }
}
__global__ __launch_bounds__(256) void reducez_k(const float* __restrict__ part,
    const float* __restrict__ efb, float* __restrict__ z,
    bf16* __restrict__ zh, bf16* __restrict__ zl)
{
    int i = blockIdx.x*blockDim.x + threadIdx.x;   // 524288
    int e = i & 511;
    float s = 0.f;
    #pragma unroll
    for (int k = 0; k < 8; k++) s += part[(size_t)k*524288 + i];
    s += efb[e];
    z[i] = s;
    bf16 hh, ll; split2(s, hh, ll); zh[i] = hh; zl[i] = ll;
}
__global__ __launch_bounds__(256) void cnorm_k(const float* __restrict__ cb,
                                               float* __restrict__ cn)
{
    int n = blockIdx.x*8 + (threadIdx.x >> 5);
    int lane = threadIdx.x & 31;
    const float* r = cb + (size_t)n*EE;
    float s = 0.f;
    for (int e = lane; e < EE; e += 32){ float v = r[e]; s += v*v; }
    #pragma unroll
    for (int o = 16; o; o >>= 1) s += __shfl_down_sync(0xffffffffu, s, o);
    if (lane == 0) cn[n] = s;
}
__global__ __launch_bounds__(256) void vq_k(
    const float* __restrict__ z, const float* __restrict__ dot,
    const float* __restrict__ cn, const float* __restrict__ cb,
    bf16* __restrict__ zqh, bf16* __restrict__ zql, float* __restrict__ lp)
{
    __shared__ float sv[256];
    __shared__ int   si[256];
    __shared__ float s_zn;
    const int b = blockIdx.x, tid = threadIdx.x;
    const float* zb = z + (size_t)b*EE;

    float zn = 0.f;
    for (int e = tid; e < EE; e += 256){ float v = zb[e]; zn += v*v; }
    sv[tid] = zn; __syncthreads();
    for (int s = 128; s > 0; s >>= 1){ if (tid < s) sv[tid] += sv[tid+s]; __syncthreads(); }
    if (tid == 0) s_zn = sv[0];
    __syncthreads();
    zn = s_zn; __syncthreads();

    const float* db = dot + (size_t)b*NEC;
    float best = 3.4e38f; int bi = 0x7fffffff;
    for (int n = tid; n < NEC; n += 256){
        float dv = (zn + cn[n]) - 2.0f * db[n];
        if (dv < best || (dv == best && n < bi)){ best = dv; bi = n; }
    }
    sv[tid] = best; si[tid] = bi; __syncthreads();
    for (int s = 128; s > 0; s >>= 1){
        if (tid < s){
            float v2 = sv[tid+s]; int i2 = si[tid+s];
            if (v2 < sv[tid] || (v2 == sv[tid] && i2 < si[tid])){ sv[tid] = v2; si[tid] = i2; }
        }
        __syncthreads();
    }
    const int idx = si[0];
    __syncthreads();

    const float* cbr = cb + (size_t)idx*EE;
    float ls = 0.f;
    for (int e = tid; e < EE; e += 256){
        float q = cbr[e];
        bf16 hh, ll; split2(q, hh, ll);
        zqh[(size_t)b*EE + e] = hh; zql[(size_t)b*EE + e] = ll;
        float d = q - zb[e]; ls += d*d;
    }
    sv[tid] = ls; __syncthreads();
    for (int s = 128; s > 0; s >>= 1){ if (tid < s) sv[tid] += sv[tid+s]; __syncthreads(); }
    if (tid == 0) lp[b] = sv[0];
}
__global__ __launch_bounds__(256) void loss_final_k(const float* __restrict__ lp,
                                                    float* __restrict__ outLoss)
{
    __shared__ float sm[256];
    int tid = threadIdx.x;
    float s = 0.f;
    #pragma unroll
    for (int i = 0; i < 4; i++) s += lp[tid + i*256];
    sm[tid] = s; __syncthreads();
    for (int st = 128; st > 0; st >>= 1){ if (tid < st) sm[tid] += sm[tid+st]; __syncthreads(); }
    if (tid == 0) *outLoss = sm[0] * 1.25f / ((float)BB * (float)EE);
}

// =====================================================================
#define SYM(p, s) do{ void* _t; cudaGetSymbolAddress(&_t, s); p = (decltype(p))_t; }while(0)

extern "C" void kernel_launch(void* const* d_in, const int* in_sizes, int n_in,
                              void* d_out, int out_size)
{
    const float* x   = (const float*)d_in[0];
    const float* ew1 = (const float*)d_in[1];  const float* eb1 = (const float*)d_in[2];
    const float* ew2 = (const float*)d_in[3];  const float* eb2 = (const float*)d_in[4];
    const float* ew3 = (const float*)d_in[5];  const float* eb3 = (const float*)d_in[6];
    const float* ew4 = (const float*)d_in[7];  const float* eb4 = (const float*)d_in[8];
    const float* efw = (const float*)d_in[9];  const float* efb = (const float*)d_in[10];
    const float* cb  = (const float*)d_in[11];
    const float* dfw = (const float*)d_in[12]; const float* dfb = (const float*)d_in[13];
    const float* dw4 = (const float*)d_in[14]; const float* db4 = (const float*)d_in[15];
    const float* dw3 = (const float*)d_in[16]; const float* db3 = (const float*)d_in[17];
    const float* dw2 = (const float*)d_in[18]; const float* db2 = (const float*)d_in[19];
    const float* dw1 = (const float*)d_in[20]; const float* db1 = (const float*)d_in[21];
    float* out = (float*)d_out;

    bf16 *aAh,*aAl,*aBh,*aBl;
    bf16 *w1h,*w1l,*w2h,*w2l,*w3h,*w3l,*w4h,*w4l;
    bf16 *d4h,*d4l,*d3h,*d3l,*d2h,*d2l,*d1h,*d1l;
    bf16 *feh,*fel,*fdh,*fdl,*cbh,*cbl,*zh,*zl,*zqh,*zql;
    float *part,*z,*dot,*cn,*lp,*dfb2;
    SYM(aAh,g_actAh); SYM(aAl,g_actAl); SYM(aBh,g_actBh); SYM(aBl,g_actBl);
    SYM(w1h,g_wA1h); SYM(w1l,g_wA1l); SYM(w2h,g_wA2h); SYM(w2l,g_wA2l);
    SYM(w3h,g_wA3h); SYM(w3l,g_wA3l); SYM(w4h,g_wA4h); SYM(w4l,g_wA4l);
    SYM(d4h,g_wD4h); SYM(d4l,g_wD4l); SYM(d3h,g_wD3h); SYM(d3l,g_wD3l);
    SYM(d2h,g_wD2h); SYM(d2l,g_wD2l); SYM(d1h,g_wD1h); SYM(d1l,g_wD1l);
    SYM(feh,g_wFEh); SYM(fel,g_wFEl); SYM(fdh,g_wFDh); SYM(fdl,g_wFDl);
    SYM(cbh,g_cbh);  SYM(cbl,g_cbl);
    SYM(zh,g_zh); SYM(zl,g_zl); SYM(zqh,g_zqh); SYM(zql,g_zql);
    SYM(part,g_part); SYM(z,g_z); SYM(dot,g_dot); SYM(cn,g_cn); SYM(lp,g_lp);
    SYM(dfb2,g_dfb2);

    cudaFuncSetAttribute(gemm_mma, cudaFuncAttributeMaxDynamicSharedMemorySize, GS);

    // launches 1-4, then gemm_mma as launch #5 (ncu -s 5 capture slot)
    xsplit_k<<<1024, 256>>>(x, aAh, aAl);
    wconv_k<<<512, 256>>>(ew1, w1h, w1l, 512, 256, 0);
    wconv_k<<<512, 256>>>(ew2, w2h, w2l, 512, 512, 0);
    wconv_k<<<512, 256>>>(ew3, w3h, w3l, 512, 512, 0);

    gemm_mma<<<dim3(NNC/128, 4, 1), 256, GS>>>(w1h, w1l, aAh, aAl, eb1,
        nullptr, aBh, aBl, nullptr, 512, 768,  768,  256, 0, 0, 1);

    wconv_k<<<512, 256>>>(ew4, w4h, w4l, 512, 512, 0);
    gemm_mma<<<dim3(NNC/128, 4, 1), 256, GS>>>(w2h, w2l, aBh, aBl, eb2,
        nullptr, aAh, aAl, nullptr, 512, 1536, 1536, 512, 0, 0, 1);
    gemm_mma<<<dim3(NNC/128, 4, 1), 256, GS>>>(w3h, w3l, aAh, aAl, eb3,
        nullptr, aBh, aBl, nullptr, 512, 1536, 1536, 512, 0, 0, 1);
    gemm_mma<<<dim3(NNC/128, 4, 1), 256, GS>>>(w4h, w4l, aBh, aBl, eb4,
        nullptr, aAh, aAl, nullptr, 512, 1536, 1536, 512, 0, 0, 1);

    // ---- remaining transforms ----
    wfe_k<<<2048, 256>>>(efw, feh, fel);
    plainsplit_k<<<2048, 256>>>(cb, cbh, cbl, (size_t)NEC*EE);
    cnorm_k<<<NEC/8, 256>>>(cb, cn);
    wfd_k<<<2048, 256>>>(dfw, fdh, fdl);
    dfb2_k<<<64, 256>>>(dfb, dfb2);
    wconv_k<<<512, 256>>>(dw4, d4h, d4l, 512, 512, 1);
    wconv_k<<<512, 256>>>(dw3, d3h, d3l, 512, 512, 1);
    wconv_k<<<512, 256>>>(dw2, d2h, d2l, 512, 512, 1);
    wconv_k<<<512, 256>>>(dw1, d1h, d1l, 256, 512, 1);

    // ---- encoder FC: M=512, N=1024, K=16384, split-K=8 ----
    gemm_mma<<<dim3(BB/128, 4, 8), 256, GS>>>(feh, fel, aAh, aAl, nullptr,
        nullptr, nullptr, nullptr, part, 512, 16384, 2048, 0, 0, 0, 0);
    reducez_k<<<2048, 256>>>(part, efb, z, zh, zl);

    // ---- VQ: dot = z @ cb^T ----
    gemm_mma<<<dim3(BB/128, NEC/128, 1), 256, GS>>>(cbh, cbl, zh, zl, nullptr,
        dot, nullptr, nullptr, nullptr, NEC, EE, EE, 0, 1, NEC, 0);
    vq_k<<<BB, 256>>>(z, dot, cn, cb, zqh, zql, lp);

    // ---- decoder FC: M=16384, N=1024, K=512 ----
    gemm_mma<<<dim3(BB/128, 16384/128, 1), 256, GS>>>(fdh, fdl, zqh, zql, dfb2,
        nullptr, aBh, aBl, nullptr, 16384, EE, EE, 0, 0, 0, 0);

    // ---- decoder convs ----
    gemm_mma<<<dim3(NNC/128, 4, 1), 256, GS>>>(d4h, d4l, aBh, aBl, db4,
        nullptr, aAh, aAl, nullptr, 512, 1536, 1536, 512, 0, 0, 1);
    gemm_mma<<<dim3(NNC/128, 4, 1), 256, GS>>>(d3h, d3l, aAh, aAl, db3,
        nullptr, aBh, aBl, nullptr, 512, 1536, 1536, 512, 0, 0, 1);
    gemm_mma<<<dim3(NNC/128, 4, 1), 256, GS>>>(d2h, d2l, aBh, aBl, db2,
        nullptr, aAh, aAl, nullptr, 512, 1536, 1536, 512, 0, 0, 1);
    gemm_mma<<<dim3(NNC/128, 2, 1), 256, GS>>>(d1h, d1l, aAh, aAl, db1,
        out, nullptr, nullptr, nullptr, 256, 1536, 1536, 512, 2, 0, 0);

    if (out_size >= RECON_N + 1)
        loss_final_k<<<1, 256>>>(lp, out + RECON_N);
}

// round 16
// speedup vs baseline: 1.2008x; 1.2008x over previous
#include <cuda_runtime.h>
#include <cuda_bf16.h>
#include <cstdint>
#include <cstddef>

typedef __nv_bfloat16 bf16;

#define BB   1024
#define CIN  256
#define HH   512
#define TT   32
#define EE   512
#define NEC  8192
#define RECON_N (BB*CIN*TT)
#define NNC  (BB*TT)          // 32768 GEMM-N for convs

#define GS 81920              // 2 buffers x 4 tiles x 10240B (also >= 8*2176*4 epilogue)

// ---------------- static device scratch ----------------
__device__ bf16 g_actAh[(size_t)NNC*HH], g_actAl[(size_t)NNC*HH];
__device__ bf16 g_actBh[(size_t)NNC*HH], g_actBl[(size_t)NNC*HH];
__device__ bf16 g_wA1h[512*768],   g_wA1l[512*768];
__device__ bf16 g_wA2h[512*1536],  g_wA2l[512*1536];
__device__ bf16 g_wA3h[512*1536],  g_wA3l[512*1536];
__device__ bf16 g_wA4h[512*1536],  g_wA4l[512*1536];
__device__ bf16 g_wD4h[512*1536],  g_wD4l[512*1536];
__device__ bf16 g_wD3h[512*1536],  g_wD3l[512*1536];
__device__ bf16 g_wD2h[512*1536],  g_wD2l[512*1536];
__device__ bf16 g_wD1h[256*1536],  g_wD1l[256*1536];
__device__ bf16 g_wFEh[(size_t)512*16384], g_wFEl[(size_t)512*16384];
__device__ bf16 g_wFDh[(size_t)16384*512], g_wFDl[(size_t)16384*512];
__device__ bf16 g_cbh[(size_t)NEC*EE],     g_cbl[(size_t)NEC*EE];
__device__ float g_dfb2[16384];
__device__ float g_part[(size_t)8*BB*EE];
__device__ float g_z[(size_t)BB*EE];
__device__ bf16  g_zh[(size_t)BB*EE],  g_zl[(size_t)BB*EE];
__device__ bf16  g_zqh[(size_t)BB*EE], g_zql[(size_t)BB*EE];
__device__ float g_dot[(size_t)BB*NEC];
__device__ float g_cn[NEC];
__device__ float g_lp[BB];

// ---------------- helpers ----------------
__device__ __forceinline__ void split2(float v, bf16& h, bf16& l){
    h = __float2bfloat16_rn(v);
    l = __float2bfloat16_rn(v - __bfloat162float(h));
}
__device__ __forceinline__ void mma_bf16(float* c, const uint32_t* a, const uint32_t* b){
    asm volatile("mma.sync.aligned.m16n8k16.row.col.f32.bf16.bf16.f32 "
        "{%0,%1,%2,%3}, {%4,%5,%6,%7}, {%8,%9}, {%0,%1,%2,%3};"
        : "+f"(c[0]), "+f"(c[1]), "+f"(c[2]), "+f"(c[3])
        : "r"(a[0]), "r"(a[1]), "r"(a[2]), "r"(a[3]), "r"(b[0]), "r"(b[1]));
}
template<int N> __device__ __forceinline__ void cp_wait(){
    asm volatile("cp.async.wait_group %0;" :: "n"(N) : "memory");
}
__device__ __forceinline__ void cp_commit(){
    asm volatile("cp.async.commit_group;" ::: "memory");
}

// stage one 128x32 x4-tile chunk into buffer `buf` via cp.async (16B, zfill halo)
__device__ __forceinline__ void stage_chunk(
    uint32_t sbU, int buf,
    const bf16* __restrict__ Ah, const bf16* __restrict__ Al,
    const bf16* __restrict__ Bh, const bf16* __restrict__ Bl,
    int m0, int n0, int k0, int K, int convC, int tid)
{
    uint32_t sb = sbU + buf*40960;
    #pragma unroll
    for (int half = 0; half < 2; half++){
        const bf16* src = half ? Al : Ah;
        uint32_t tb = sb + half*10240;
        #pragma unroll
        for (int it = 0; it < 2; it++){
            int task = tid + it*256;
            int r = task >> 2, seg = task & 3;
            const void* g = src + (size_t)(m0 + r)*K + k0 + seg*8;
            asm volatile("cp.async.cg.shared.global [%0], [%1], 16;"
                :: "r"(tb + r*80 + seg*16), "l"(g));
        }
    }
    #pragma unroll
    for (int half = 0; half < 2; half++){
        const bf16* src = half ? Bl : Bh;
        uint32_t tb = sb + 20480 + half*10240;
        #pragma unroll
        for (int it = 0; it < 2; it++){
            int task = tid + it*256;
            int r = task >> 2, seg = task & 3;
            int n = n0 + r;
            const bf16* g; int sz = 16;
            if (convC){
                int t = n & 31, ks2 = k0 / convC, kr = k0 - ks2*convC;
                if ((unsigned)(t + ks2 - 1) < 32u)
                    g = src + (size_t)(n + ks2 - 1)*convC + kr + seg*8;
                else { g = src; sz = 0; }
            } else {
                g = src + (size_t)n*K + k0 + seg*8;
            }
            asm volatile("cp.async.cg.shared.global [%0], [%1], 16, %2;"
                :: "r"(tb + r*80 + seg*16), "l"((const void*)g), "r"(sz));
        }
    }
}

// =====================================================================
// split-bf16 NT GEMM via mma.sync (R4 engine) + smem-transposed act epilogue.
// grid = (Ntot/128, Mtot/128, zsplit). convC: implicit im2col on B rows.
// fmode 1 -> outF[n*ldc+m]; fmode 2 -> outF[(n>>5)*Mtot*32+m*32+(n&31)];
// oH/oL path (fmode 0): coalesced 16B stores via smem transpose.
// zsplit>1: fp32 partials.
// =====================================================================
__global__ void __launch_bounds__(256) gemm_mma(
    const bf16* __restrict__ Ah, const bf16* __restrict__ Al,
    const bf16* __restrict__ Bh, const bf16* __restrict__ Bl,
    const float* __restrict__ bias, float* __restrict__ outF,
    bf16* __restrict__ outH, bf16* __restrict__ outL,
    float* __restrict__ partBase,
    int Mtot, int K, int kseg, int convC, int fmode, int ldc, int relu)
{
    extern __shared__ char smem[];
    const uint32_t sbU = (uint32_t)__cvta_generic_to_shared(smem);
    const int tid  = threadIdx.x;
    const int lane = tid & 31, wid = tid >> 5;
    const int wm = wid >> 2, wn = wid & 3;     // 2 x 4 warps, 64x32 each
    const int m0 = blockIdx.y * 128;
    const int n0 = blockIdx.x * 128;
    const int kb = blockIdx.z * kseg;
    const int NC = kseg / 32;

    float acc[4][4][4];
    #pragma unroll
    for (int i = 0; i < 4; i++)
        #pragma unroll
        for (int j = 0; j < 4; j++)
            #pragma unroll
            for (int r = 0; r < 4; r++) acc[i][j][r] = 0.f;

    stage_chunk(sbU, 0, Ah, Al, Bh, Bl, m0, n0, kb, K, convC, tid);
    cp_commit();
    if (NC > 1){
        stage_chunk(sbU, 1, Ah, Al, Bh, Bl, m0, n0, kb + 32, K, convC, tid);
        cp_commit();
    }

    const uint32_t* sw = (const uint32_t*)smem;

    for (int ci = 0; ci < NC; ci++){
        if (ci + 1 < NC) cp_wait<1>(); else cp_wait<0>();
        __syncthreads();

        const uint32_t* sb  = sw + (ci & 1) * 10240;
        const uint32_t* sAh = sb;
        const uint32_t* sAl = sb + 2560;
        const uint32_t* sBh = sb + 5120;
        const uint32_t* sBl = sb + 7680;

        #pragma unroll
        for (int s = 0; s < 2; s++){
            const int kwo = s*8;
            uint32_t ah[4][4], al[4][4], bh[4][2], bl[4][2];
            #pragma unroll
            for (int i = 0; i < 4; i++){
                int wb = (wm*64 + i*16 + (lane >> 2))*20 + kwo + (lane & 3);
                ah[i][0] = sAh[wb];       ah[i][1] = sAh[wb + 160];
                ah[i][2] = sAh[wb + 4];   ah[i][3] = sAh[wb + 164];
                al[i][0] = sAl[wb];       al[i][1] = sAl[wb + 160];
                al[i][2] = sAl[wb + 4];   al[i][3] = sAl[wb + 164];
            }
            #pragma unroll
            for (int j = 0; j < 4; j++){
                int wb = (wn*32 + j*8 + (lane >> 2))*20 + kwo + (lane & 3);
                bh[j][0] = sBh[wb];  bh[j][1] = sBh[wb + 4];
                bl[j][0] = sBl[wb];  bl[j][1] = sBl[wb + 4];
            }
            #pragma unroll
            for (int i = 0; i < 4; i++)
                #pragma unroll
                for (int j = 0; j < 4; j++){
                    mma_bf16(acc[i][j], ah[i], bh[j]);
                    mma_bf16(acc[i][j], ah[i], bl[j]);
                    mma_bf16(acc[i][j], al[i], bh[j]);
                }
        }
        __syncthreads();
        if (ci + 2 < NC){
            stage_chunk(sbU, ci & 1, Ah, Al, Bh, Bl, m0, n0,
                        kb + (ci + 2)*32, K, convC, tid);
            cp_commit();
        }
    }

    // ---- epilogue ----
    const bool dosplit = (gridDim.z > 1);
    if (outH && !dosplit){
        // smem transpose: per-warp 32n x 64m fp32 region, stride 68 (conflict-free)
        float* wsm = (float*)smem;
        float* myw = wsm + wid*2176;
        #pragma unroll
        for (int i = 0; i < 4; i++){
            const int mgA = m0 + wm*64 + i*16 + (lane >> 2);
            const float bvA = bias ? bias[mgA] : 0.f;
            const float bvB = bias ? bias[mgA + 8] : 0.f;
            #pragma unroll
            for (int j = 0; j < 4; j++){
                float v0 = acc[i][j][0] + bvA, v1 = acc[i][j][1] + bvA;
                float v2 = acc[i][j][2] + bvB, v3 = acc[i][j][3] + bvB;
                if (relu){
                    v0 = fmaxf(v0, 0.f); v1 = fmaxf(v1, 0.f);
                    v2 = fmaxf(v2, 0.f); v3 = fmaxf(v3, 0.f);
                }
                const int nl = j*8 + (lane & 3)*2;
                const int ml = i*16 + (lane >> 2);
                myw[nl*68 + ml]           = v0;
                myw[(nl + 1)*68 + ml]     = v1;
                myw[nl*68 + ml + 8]       = v2;
                myw[(nl + 1)*68 + ml + 8] = v3;
            }
        }
        __syncthreads();
        #pragma unroll
        for (int pass = 0; pass < 8; pass++){
            const int nIdx = pass*16 + (tid >> 4);
            const int m8   = (tid & 15)*8;
            const int wsel = (m8 >> 6)*4 + (nIdx >> 5);
            const float* src = wsm + wsel*2176 + (nIdx & 31)*68 + (m8 & 63);
            uint32_t hw[4], lw[4];
            #pragma unroll
            for (int k = 0; k < 4; k++){
                bf16 h0, l0, h1, l1;
                split2(src[2*k],     h0, l0);
                split2(src[2*k + 1], h1, l1);
                __nv_bfloat162 hp = {h0, h1}, lp = {l0, l1};
                hw[k] = *(uint32_t*)&hp;
                lw[k] = *(uint32_t*)&lp;
            }
            size_t base = (size_t)(n0 + nIdx)*Mtot + m0 + m8;
            *(uint4*)(outH + base) = make_uint4(hw[0], hw[1], hw[2], hw[3]);
            *(uint4*)(outL + base) = make_uint4(lw[0], lw[1], lw[2], lw[3]);
        }
        return;
    }
    // fp32 output paths (dot / split-K partials / recon)
    {
        const int nTot = gridDim.x * 128;
        float* fO = outF; int fm = fmode; int lld = ldc;
        if (dosplit){
            fO = partBase + (size_t)blockIdx.z * Mtot * nTot;
            fm = 1; lld = Mtot;
        }
        #pragma unroll
        for (int i = 0; i < 4; i++){
            const int mA = m0 + wm*64 + i*16 + (lane >> 2);
            const int mB = mA + 8;
            const float bvA = (!dosplit && bias) ? bias[mA] : 0.f;
            const float bvB = (!dosplit && bias) ? bias[mB] : 0.f;
            #pragma unroll
            for (int j = 0; j < 4; j++){
                const int nb = n0 + wn*32 + j*8 + (lane & 3)*2;
                float v[4];
                v[0] = acc[i][j][0] + bvA;  v[1] = acc[i][j][1] + bvA;
                v[2] = acc[i][j][2] + bvB;  v[3] = acc[i][j][3] + bvB;
                if (relu){
                    #pragma unroll
                    for (int r = 0; r < 4; r++) v[r] = fmaxf(v[r], 0.f);
                }
                const int mm[4] = {mA, mA, mB, mB};
                const int nn[4] = {nb, nb + 1, nb, nb + 1};
                #pragma unroll
                for (int r = 0; r < 4; r++){
                    const int m = mm[r], n = nn[r];
                    if (fm == 1)
                        fO[(size_t)n * lld + m] = v[r];
                    else if (fm == 2)
                        fO[(size_t)(n >> 5) * ((size_t)Mtot * 32) + (size_t)m * 32 + (n & 31)] = v[r];
                }
            }
        }
    }
}

// ---------------- transforms ----------------
__global__ __launch_bounds__(256) void wconv_k(const float* __restrict__ w,
    bf16* __restrict__ h, bf16* __restrict__ l, int O, int C, int isT)
{
    int total = O * C * 3;
    for (int i = blockIdx.x*blockDim.x + threadIdx.x; i < total; i += gridDim.x*blockDim.x){
        int o = i / (C*3), r = i % (C*3), c = r / 3, k = r % 3;
        float v = isT ? w[((size_t)c*O + o)*3 + (2 - k)] : w[i];
        size_t d = (size_t)o*(3*C) + k*C + c;
        bf16 hh, ll; split2(v, hh, ll); h[d] = hh; l[d] = ll;
    }
}
__global__ __launch_bounds__(256) void wfe_k(const float* __restrict__ w,
    bf16* __restrict__ h, bf16* __restrict__ l)
{
    size_t total = (size_t)512*16384;
    for (size_t i = blockIdx.x*(size_t)blockDim.x + threadIdx.x; i < total;
         i += (size_t)gridDim.x*blockDim.x){
        int e = (int)(i >> 14), fp = (int)(i & 16383);
        int t = fp >> 9, c = fp & 511;
        float v = w[(size_t)e*16384 + c*32 + t];
        bf16 hh, ll; split2(v, hh, ll); h[i] = hh; l[i] = ll;
    }
}
__global__ __launch_bounds__(256) void wfd_k(const float* __restrict__ w,
    bf16* __restrict__ h, bf16* __restrict__ l)
{
    size_t total = (size_t)16384*512;
    for (size_t i = blockIdx.x*(size_t)blockDim.x + threadIdx.x; i < total;
         i += (size_t)gridDim.x*blockDim.x){
        int fp = (int)(i >> 9), e = (int)(i & 511);
        int t = fp >> 9, c = fp & 511;
        float v = w[((size_t)(c*32 + t))*512 + e];
        bf16 hh, ll; split2(v, hh, ll); h[i] = hh; l[i] = ll;
    }
}
__global__ __launch_bounds__(256) void dfb2_k(const float* __restrict__ b,
    float* __restrict__ b2)
{
    int i = blockIdx.x*blockDim.x + threadIdx.x;
    int t = i >> 9, c = i & 511;
    b2[i] = b[c*32 + t];
}
__global__ __launch_bounds__(256) void plainsplit_k(const float* __restrict__ s,
    bf16* __restrict__ h, bf16* __restrict__ l, size_t n)
{
    for (size_t i = blockIdx.x*(size_t)blockDim.x + threadIdx.x; i < n;
         i += (size_t)gridDim.x*blockDim.x){
        bf16 hh, ll; split2(s[i], hh, ll); h[i] = hh; l[i] = ll;
    }
}
__global__ __launch_bounds__(256) void xsplit_k(const float* __restrict__ x,
    bf16* __restrict__ h, bf16* __restrict__ l)
{
    size_t total = (size_t)BB*CIN*TT;
    for (size_t i = blockIdx.x*(size_t)blockDim.x + threadIdx.x; i < total;
         i += (size_t)gridDim.x*blockDim.x){
        int b = (int)(i >> 13), r = (int)(i & 8191);
        int c = r >> 5, t = r & 31;
        size_t d = (size_t)(b*32 + t)*256 + c;
        bf16 hh, ll; split2(x[i], hh, ll); h[d] = hh; l[d] = ll;
    }
}
__global__ __launch_bounds__(256) void reducez_k(const float* __restrict__ part,
    const float* __restrict__ efb, float* __restrict__ z,
    bf16* __restrict__ zh, bf16* __restrict__ zl)
{
    int i = blockIdx.x*blockDim.x + threadIdx.x;   // 524288
    int e = i & 511;
    float s = 0.f;
    #pragma unroll
    for (int k = 0; k < 8; k++) s += part[(size_t)k*524288 + i];
    s += efb[e];
    z[i] = s;
    bf16 hh, ll; split2(s, hh, ll); zh[i] = hh; zl[i] = ll;
}
__global__ __launch_bounds__(256) void cnorm_k(const float* __restrict__ cb,
                                               float* __restrict__ cn)
{
    int n = blockIdx.x*8 + (threadIdx.x >> 5);
    int lane = threadIdx.x & 31;
    const float* r = cb + (size_t)n*EE;
    float s = 0.f;
    for (int e = lane; e < EE; e += 32){ float v = r[e]; s += v*v; }
    #pragma unroll
    for (int o = 16; o; o >>= 1) s += __shfl_down_sync(0xffffffffu, s, o);
    if (lane == 0) cn[n] = s;
}
__global__ __launch_bounds__(256) void vq_k(
    const float* __restrict__ z, const float* __restrict__ dot,
    const float* __restrict__ cn, const float* __restrict__ cb,
    bf16* __restrict__ zqh, bf16* __restrict__ zql, float* __restrict__ lp)
{
    __shared__ float sv[256];
    __shared__ int   si[256];
    __shared__ float s_zn;
    const int b = blockIdx.x, tid = threadIdx.x;
    const float* zb = z + (size_t)b*EE;

    float zn = 0.f;
    for (int e = tid; e < EE; e += 256){ float v = zb[e]; zn += v*v; }
    sv[tid] = zn; __syncthreads();
    for (int s = 128; s > 0; s >>= 1){ if (tid < s) sv[tid] += sv[tid+s]; __syncthreads(); }
    if (tid == 0) s_zn = sv[0];
    __syncthreads();
    zn = s_zn; __syncthreads();

    const float* db = dot + (size_t)b*NEC;
    float best = 3.4e38f; int bi = 0x7fffffff;
    for (int n = tid; n < NEC; n += 256){
        float dv = (zn + cn[n]) - 2.0f * db[n];
        if (dv < best || (dv == best && n < bi)){ best = dv; bi = n; }
    }
    sv[tid] = best; si[tid] = bi; __syncthreads();
    for (int s = 128; s > 0; s >>= 1){
        if (tid < s){
            float v2 = sv[tid+s]; int i2 = si[tid+s];
            if (v2 < sv[tid] || (v2 == sv[tid] && i2 < si[tid])){ sv[tid] = v2; si[tid] = i2; }
        }
        __syncthreads();
    }
    const int idx = si[0];
    __syncthreads();

    const float* cbr = cb + (size_t)idx*EE;
    float ls = 0.f;
    for (int e = tid; e < EE; e += 256){
        float q = cbr[e];
        bf16 hh, ll; split2(q, hh, ll);
        zqh[(size_t)b*EE + e] = hh; zql[(size_t)b*EE + e] = ll;
        float d = q - zb[e]; ls += d*d;
    }
    sv[tid] = ls; __syncthreads();
    for (int s = 128; s > 0; s >>= 1){ if (tid < s) sv[tid] += sv[tid+s]; __syncthreads(); }
    if (tid == 0) lp[b] = sv[0];
}
__global__ __launch_bounds__(256) void loss_final_k(const float* __restrict__ lp,
                                                    float* __restrict__ outLoss)
{
    __shared__ float sm[256];
    int tid = threadIdx.x;
    float s = 0.f;
    #pragma unroll
    for (int i = 0; i < 4; i++) s += lp[tid + i*256];
    sm[tid] = s; __syncthreads();
    for (int st = 128; st > 0; st >>= 1){ if (tid < st) sm[tid] += sm[tid+st]; __syncthreads(); }
    if (tid == 0) *outLoss = sm[0] * 1.25f / ((float)BB * (float)EE);
}

// =====================================================================
#define SYM(p, s) do{ void* _t; cudaGetSymbolAddress(&_t, s); p = (decltype(p))_t; }while(0)

extern "C" void kernel_launch(void* const* d_in, const int* in_sizes, int n_in,
                              void* d_out, int out_size)
{
    const float* x   = (const float*)d_in[0];
    const float* ew1 = (const float*)d_in[1];  const float* eb1 = (const float*)d_in[2];
    const float* ew2 = (const float*)d_in[3];  const float* eb2 = (const float*)d_in[4];
    const float* ew3 = (const float*)d_in[5];  const float* eb3 = (const float*)d_in[6];
    const float* ew4 = (const float*)d_in[7];  const float* eb4 = (const float*)d_in[8];
    const float* efw = (const float*)d_in[9];  const float* efb = (const float*)d_in[10];
    const float* cb  = (const float*)d_in[11];
    const float* dfw = (const float*)d_in[12]; const float* dfb = (const float*)d_in[13];
    const float* dw4 = (const float*)d_in[14]; const float* db4 = (const float*)d_in[15];
    const float* dw3 = (const float*)d_in[16]; const float* db3 = (const float*)d_in[17];
    const float* dw2 = (const float*)d_in[18]; const float* db2 = (const float*)d_in[19];
    const float* dw1 = (const float*)d_in[20]; const float* db1 = (const float*)d_in[21];
    float* out = (float*)d_out;

    bf16 *aAh,*aAl,*aBh,*aBl;
    bf16 *w1h,*w1l,*w2h,*w2l,*w3h,*w3l,*w4h,*w4l;
    bf16 *d4h,*d4l,*d3h,*d3l,*d2h,*d2l,*d1h,*d1l;
    bf16 *feh,*fel,*fdh,*fdl,*cbh,*cbl,*zh,*zl,*zqh,*zql;
    float *part,*z,*dot,*cn,*lp,*dfb2;
    SYM(aAh,g_actAh); SYM(aAl,g_actAl); SYM(aBh,g_actBh); SYM(aBl,g_actBl);
    SYM(w1h,g_wA1h); SYM(w1l,g_wA1l); SYM(w2h,g_wA2h); SYM(w2l,g_wA2l);
    SYM(w3h,g_wA3h); SYM(w3l,g_wA3l); SYM(w4h,g_wA4h); SYM(w4l,g_wA4l);
    SYM(d4h,g_wD4h); SYM(d4l,g_wD4l); SYM(d3h,g_wD3h); SYM(d3l,g_wD3l);
    SYM(d2h,g_wD2h); SYM(d2l,g_wD2l); SYM(d1h,g_wD1h); SYM(d1l,g_wD1l);
    SYM(feh,g_wFEh); SYM(fel,g_wFEl); SYM(fdh,g_wFDh); SYM(fdl,g_wFDl);
    SYM(cbh,g_cbh);  SYM(cbl,g_cbl);
    SYM(zh,g_zh); SYM(zl,g_zl); SYM(zqh,g_zqh); SYM(zql,g_zql);
    SYM(part,g_part); SYM(z,g_z); SYM(dot,g_dot); SYM(cn,g_cn); SYM(lp,g_lp);
    SYM(dfb2,g_dfb2);

    cudaFuncSetAttribute(gemm_mma, cudaFuncAttributeMaxDynamicSharedMemorySize, GS);

    // launches 1-5, then gemm_mma as launch #6 (ncu -s 5 skips 5, captures #6)
    xsplit_k<<<1024, 256>>>(x, aAh, aAl);
    wconv_k<<<512, 256>>>(ew1, w1h, w1l, 512, 256, 0);
    wconv_k<<<512, 256>>>(ew2, w2h, w2l, 512, 512, 0);
    wconv_k<<<512, 256>>>(ew3, w3h, w3l, 512, 512, 0);
    wconv_k<<<512, 256>>>(ew4, w4h, w4l, 512, 512, 0);

    // ---- encoder convs ----
    gemm_mma<<<dim3(NNC/128, 4, 1), 256, GS>>>(w1h, w1l, aAh, aAl, eb1,
        nullptr, aBh, aBl, nullptr, 512, 768,  768,  256, 0, 0, 1);
    gemm_mma<<<dim3(NNC/128, 4, 1), 256, GS>>>(w2h, w2l, aBh, aBl, eb2,
        nullptr, aAh, aAl, nullptr, 512, 1536, 1536, 512, 0, 0, 1);
    gemm_mma<<<dim3(NNC/128, 4, 1), 256, GS>>>(w3h, w3l, aAh, aAl, eb3,
        nullptr, aBh, aBl, nullptr, 512, 1536, 1536, 512, 0, 0, 1);
    gemm_mma<<<dim3(NNC/128, 4, 1), 256, GS>>>(w4h, w4l, aBh, aBl, eb4,
        nullptr, aAh, aAl, nullptr, 512, 1536, 1536, 512, 0, 0, 1);

    // ---- remaining transforms ----
    wfe_k<<<2048, 256>>>(efw, feh, fel);
    plainsplit_k<<<2048, 256>>>(cb, cbh, cbl, (size_t)NEC*EE);
    cnorm_k<<<NEC/8, 256>>>(cb, cn);
    wfd_k<<<2048, 256>>>(dfw, fdh, fdl);
    dfb2_k<<<64, 256>>>(dfb, dfb2);
    wconv_k<<<512, 256>>>(dw4, d4h, d4l, 512, 512, 1);
    wconv_k<<<512, 256>>>(dw3, d3h, d3l, 512, 512, 1);
    wconv_k<<<512, 256>>>(dw2, d2h, d2l, 512, 512, 1);
    wconv_k<<<512, 256>>>(dw1, d1h, d1l, 256, 512, 1);

    // ---- encoder FC: M=512, N=1024, K=16384, split-K=8 ----
    gemm_mma<<<dim3(BB/128, 4, 8), 256, GS>>>(feh, fel, aAh, aAl, nullptr,
        nullptr, nullptr, nullptr, part, 512, 16384, 2048, 0, 0, 0, 0);
    reducez_k<<<2048, 256>>>(part, efb, z, zh, zl);

    // ---- VQ: dot = z @ cb^T ----
    gemm_mma<<<dim3(BB/128, NEC/128, 1), 256, GS>>>(cbh, cbl, zh, zl, nullptr,
        dot, nullptr, nullptr, nullptr, NEC, EE, EE, 0, 1, NEC, 0);
    vq_k<<<BB, 256>>>(z, dot, cn, cb, zqh, zql, lp);

    // ---- decoder FC: M=16384, N=1024, K=512 ----
    gemm_mma<<<dim3(BB/128, 16384/128, 1), 256, GS>>>(fdh, fdl, zqh, zql, dfb2,
        nullptr, aBh, aBl, nullptr, 16384, EE, EE, 0, 0, 0, 0);

    // ---- decoder convs ----
    gemm_mma<<<dim3(NNC/128, 4, 1), 256, GS>>>(d4h, d4l, aBh, aBl, db4,
        nullptr, aAh, aAl, nullptr, 512, 1536, 1536, 512, 0, 0, 1);
    gemm_mma<<<dim3(NNC/128, 4, 1), 256, GS>>>(d3h, d3l, aAh, aAl, db3,
        nullptr, aBh, aBl, nullptr, 512, 1536, 1536, 512, 0, 0, 1);
    gemm_mma<<<dim3(NNC/128, 4, 1), 256, GS>>>(d2h, d2l, aBh, aBl, db2,
        nullptr, aAh, aAl, nullptr, 512, 1536, 1536, 512, 0, 0, 1);
    gemm_mma<<<dim3(NNC/128, 2, 1), 256, GS>>>(d1h, d1l, aAh, aAl, db1,
        out, nullptr, nullptr, nullptr, 256, 1536, 1536, 512, 2, 0, 0);

    if (out_size >= RECON_N + 1)
        loss_final_k<<<1, 256>>>(lp, out + RECON_N);
}

// round 17
// speedup vs baseline: 1.4936x; 1.2439x over previous
#include <cuda_runtime.h>
#include <cuda_bf16.h>
#include <cuda_fp16.h>
#include <cstdint>
#include <cstddef>

typedef __nv_bfloat16 bf16;

#define BB   1024
#define CIN  256
#define HH   512
#define TT   32
#define EE   512
#define NEC  8192
#define RECON_N (BB*CIN*TT)
#define NNC  (BB*TT)
#define QSC  4096.0f

#define GS 81920              // 2 buffers x 4 tiles x 10240B (>= 8*2176*4 epi)

// ---------------- static device scratch ----------------
__device__ bf16 g_actAh[(size_t)NNC*HH], g_actAl[(size_t)NNC*HH];
__device__ bf16 g_actBh[(size_t)NNC*HH], g_actBl[(size_t)NNC*HH];
__device__ bf16 g_wA1h[512*768],   g_wA1l[512*768];
__device__ bf16 g_wA2h[512*1536],  g_wA2l[512*1536];
__device__ bf16 g_wA3h[512*1536],  g_wA3l[512*1536];
__device__ bf16 g_wA4h[512*1536],  g_wA4l[512*1536];
__device__ __half g_wD4h[512*1536],  g_wD4l[512*1536];
__device__ __half g_wD3h[512*1536],  g_wD3l[512*1536];
__device__ __half g_wD2h[512*1536],  g_wD2l[512*1536];
__device__ __half g_wD1h[256*1536],  g_wD1l[256*1536];
__device__ bf16 g_wFEh[(size_t)512*16384], g_wFEl[(size_t)512*16384];
__device__ __half g_wFD[(size_t)16384*512];
__device__ bf16 g_cbh[(size_t)NEC*EE],     g_cbl[(size_t)NEC*EE];
__device__ float g_dfb2[16384];
__device__ float g_part[(size_t)8*BB*EE];
__device__ float g_z[(size_t)BB*EE];
__device__ bf16  g_zh[(size_t)BB*EE],  g_zl[(size_t)BB*EE];
__device__ __half g_zqh[(size_t)BB*EE], g_zql[(size_t)BB*EE]; // zq*QSC pair
__device__ float g_dot[(size_t)BB*NEC];
__device__ float g_cn[NEC];
__device__ float g_lp[BB];

// ---------------- helpers ----------------
__device__ __forceinline__ void split2(float v, bf16& h, bf16& l){
    h = __float2bfloat16_rn(v);
    l = __float2bfloat16_rn(v - __bfloat162float(h));
}
__device__ __forceinline__ void split2h(float v, __half& h, __half& l){
    h = __float2half_rn(v);
    l = __float2half_rn(v - __half2float(h));
}
__device__ __forceinline__ void mma_bf(float* c, const uint32_t* a, const uint32_t* b){
    asm volatile("mma.sync.aligned.m16n8k16.row.col.f32.bf16.bf16.f32 "
        "{%0,%1,%2,%3}, {%4,%5,%6,%7}, {%8,%9}, {%0,%1,%2,%3};"
        : "+f"(c[0]), "+f"(c[1]), "+f"(c[2]), "+f"(c[3])
        : "r"(a[0]), "r"(a[1]), "r"(a[2]), "r"(a[3]), "r"(b[0]), "r"(b[1]));
}
__device__ __forceinline__ void mma_fp(float* c, const uint32_t* a, const uint32_t* b){
    asm volatile("mma.sync.aligned.m16n8k16.row.col.f32.f16.f16.f32 "
        "{%0,%1,%2,%3}, {%4,%5,%6,%7}, {%8,%9}, {%0,%1,%2,%3};"
        : "+f"(c[0]), "+f"(c[1]), "+f"(c[2]), "+f"(c[3])
        : "r"(a[0]), "r"(a[1]), "r"(a[2]), "r"(a[3]), "r"(b[0]), "r"(b[1]));
}
template<int N> __device__ __forceinline__ void cp_wait(){
    asm volatile("cp.async.wait_group %0;" :: "n"(N) : "memory");
}
__device__ __forceinline__ void cp_commit(){
    asm volatile("cp.async.commit_group;" ::: "memory");
}

// stage one 128x32 chunk. Tiles: A@0, Al@10240, Bh@20480, Bl@30720.
// MODE 0: A,Al,Bh,Bl. MODE 1: A,Al,Bh. MODE 2: A,Bh,Bl.
template<int MODE>
__device__ __forceinline__ void stage_chunk(
    uint32_t sbU, int buf,
    const uint16_t* __restrict__ Ah, const uint16_t* __restrict__ Al,
    const uint16_t* __restrict__ Bh, const uint16_t* __restrict__ Bl,
    int m0, int n0, int k0, int K, int convC, int tid)
{
    uint32_t sb = sbU + buf*40960;
    #pragma unroll
    for (int it = 0; it < 2; it++){
        int task = tid + it*256;
        int r = task >> 2, seg = task & 3;
        size_t go = (size_t)(m0 + r)*K + k0 + seg*8;
        uint32_t so = r*80 + seg*16;
        asm volatile("cp.async.cg.shared.global [%0], [%1], 16;"
            :: "r"(sb + so), "l"((const void*)(Ah + go)));
        if (MODE != 2)
            asm volatile("cp.async.cg.shared.global [%0], [%1], 16;"
                :: "r"(sb + 10240 + so), "l"((const void*)(Al + go)));
    }
    #pragma unroll
    for (int it = 0; it < 2; it++){
        int task = tid + it*256;
        int r = task >> 2, seg = task & 3;
        int n = n0 + r;
        uint32_t so = r*80 + seg*16;
        const uint16_t *gh = Bh, *gl = Bh; int sz = 16;
        if (convC){
            int t = n & 31, ks2 = k0 / convC, kr = k0 - ks2*convC;
            if ((unsigned)(t + ks2 - 1) < 32u){
                size_t go = (size_t)(n + ks2 - 1)*convC + kr + seg*8;
                gh = Bh + go; if (MODE != 1) gl = Bl + go;
            } else sz = 0;
        } else {
            size_t go = (size_t)n*K + k0 + seg*8;
            gh = Bh + go; if (MODE != 1) gl = Bl + go;
        }
        asm volatile("cp.async.cg.shared.global [%0], [%1], 16, %2;"
            :: "r"(sb + 20480 + so), "l"((const void*)gh), "r"(sz));
        if (MODE != 1)
            asm volatile("cp.async.cg.shared.global [%0], [%1], 16, %2;"
                :: "r"(sb + 30720 + so), "l"((const void*)gl), "r"(sz));
    }
}

// =====================================================================
// NT GEMM. MODE 0: bf16 3-term (ah·bh+ah·bl+al·bh), act out = bf16 pair.
// MODE 1: fp16 2-term A-pair (ah·bh+al·bh), act out = fp16 single.
// MODE 2: fp16 2-term B-pair (ah·bh+ah·bl), act out = fp16 single.
// v = acc*accScale + bias[m]*bScale. fmode 1: outF[n*ldc+m];
// fmode 2: outF[(n>>5)*Mtot*32+m*32+(n&31)]. zsplit>1: fp32 partials.
// =====================================================================
template<int MODE>
__global__ void __launch_bounds__(256) gemm_mma(
    const uint16_t* __restrict__ Ah, const uint16_t* __restrict__ Al,
    const uint16_t* __restrict__ Bh, const uint16_t* __restrict__ Bl,
    const float* __restrict__ bias, float* __restrict__ outF,
    uint16_t* __restrict__ outH, uint16_t* __restrict__ outL,
    float* __restrict__ partBase,
    int Mtot, int K, int kseg, int convC, int fmode, int ldc, int relu,
    float accScale, float bScale)
{
    extern __shared__ char smem[];
    const uint32_t sbU = (uint32_t)__cvta_generic_to_shared(smem);
    const int tid  = threadIdx.x;
    const int lane = tid & 31, wid = tid >> 5;
    const int wm = wid >> 2, wn = wid & 3;
    const int m0 = blockIdx.y * 128;
    const int n0 = blockIdx.x * 128;
    const int kb = blockIdx.z * kseg;
    const int NC = kseg / 32;

    float acc[4][4][4];
    #pragma unroll
    for (int i = 0; i < 4; i++)
        #pragma unroll
        for (int j = 0; j < 4; j++)
            #pragma unroll
            for (int r = 0; r < 4; r++) acc[i][j][r] = 0.f;

    stage_chunk<MODE>(sbU, 0, Ah, Al, Bh, Bl, m0, n0, kb, K, convC, tid);
    cp_commit();
    if (NC > 1){
        stage_chunk<MODE>(sbU, 1, Ah, Al, Bh, Bl, m0, n0, kb + 32, K, convC, tid);
        cp_commit();
    }

    const uint32_t* sw = (const uint32_t*)smem;

    for (int ci = 0; ci < NC; ci++){
        if (ci + 1 < NC) cp_wait<1>(); else cp_wait<0>();
        __syncthreads();

        const uint32_t* sb  = sw + (ci & 1) * 10240;
        const uint32_t* sAh = sb;
        const uint32_t* sAl = sb + 2560;
        const uint32_t* sBh = sb + 5120;
        const uint32_t* sBl = sb + 7680;

        #pragma unroll
        for (int s = 0; s < 2; s++){
            const int kwo = s*8;
            uint32_t ah[4][4], a2[4][4], bh[4][2], b2[4][2];
            #pragma unroll
            for (int i = 0; i < 4; i++){
                int wb = (wm*64 + i*16 + (lane >> 2))*20 + kwo + (lane & 3);
                ah[i][0] = sAh[wb];       ah[i][1] = sAh[wb + 160];
                ah[i][2] = sAh[wb + 4];   ah[i][3] = sAh[wb + 164];
                if (MODE != 2){
                    a2[i][0] = sAl[wb];     a2[i][1] = sAl[wb + 160];
                    a2[i][2] = sAl[wb + 4]; a2[i][3] = sAl[wb + 164];
                }
            }
            #pragma unroll
            for (int j = 0; j < 4; j++){
                int wb = (wn*32 + j*8 + (lane >> 2))*20 + kwo + (lane & 3);
                bh[j][0] = sBh[wb];  bh[j][1] = sBh[wb + 4];
                if (MODE != 1){
                    b2[j][0] = sBl[wb];  b2[j][1] = sBl[wb + 4];
                }
            }
            #pragma unroll
            for (int i = 0; i < 4; i++)
                #pragma unroll
                for (int j = 0; j < 4; j++){
                    if (MODE == 0){
                        mma_bf(acc[i][j], ah[i], bh[j]);
                        mma_bf(acc[i][j], ah[i], b2[j]);
                        mma_bf(acc[i][j], a2[i], bh[j]);
                    } else if (MODE == 1){
                        mma_fp(acc[i][j], ah[i], bh[j]);
                        mma_fp(acc[i][j], a2[i], bh[j]);
                    } else {
                        mma_fp(acc[i][j], ah[i], bh[j]);
                        mma_fp(acc[i][j], ah[i], b2[j]);
                    }
                }
        }
        __syncthreads();
        if (ci + 2 < NC){
            stage_chunk<MODE>(sbU, ci & 1, Ah, Al, Bh, Bl, m0, n0,
                              kb + (ci + 2)*32, K, convC, tid);
            cp_commit();
        }
    }

    const bool dosplit = (gridDim.z > 1);
    if (outH && !dosplit){
        // smem transpose, stride 68 (conflict-free), then coalesced 16B stores
        float* wsm = (float*)smem;
        float* myw = wsm + wid*2176;
        #pragma unroll
        for (int i = 0; i < 4; i++){
            const int mgA = m0 + wm*64 + i*16 + (lane >> 2);
            const float bvA = bias ? bias[mgA]*bScale : 0.f;
            const float bvB = bias ? bias[mgA + 8]*bScale : 0.f;
            #pragma unroll
            for (int j = 0; j < 4; j++){
                float v0 = acc[i][j][0]*accScale + bvA, v1 = acc[i][j][1]*accScale + bvA;
                float v2 = acc[i][j][2]*accScale + bvB, v3 = acc[i][j][3]*accScale + bvB;
                if (relu){
                    v0 = fmaxf(v0, 0.f); v1 = fmaxf(v1, 0.f);
                    v2 = fmaxf(v2, 0.f); v3 = fmaxf(v3, 0.f);
                }
                const int nl = j*8 + (lane & 3)*2;
                const int ml = i*16 + (lane >> 2);
                myw[nl*68 + ml]           = v0;
                myw[(nl + 1)*68 + ml]     = v1;
                myw[nl*68 + ml + 8]       = v2;
                myw[(nl + 1)*68 + ml + 8] = v3;
            }
        }
        __syncthreads();
        #pragma unroll
        for (int pass = 0; pass < 8; pass++){
            const int nIdx = pass*16 + (tid >> 4);
            const int m8   = (tid & 15)*8;
            const int wsel = (m8 >> 6)*4 + (nIdx >> 5);
            const float* src = wsm + wsel*2176 + (nIdx & 31)*68 + (m8 & 63);
            size_t base = (size_t)(n0 + nIdx)*Mtot + m0 + m8;
            if (MODE == 0){
                uint32_t hw[4], lw[4];
                #pragma unroll
                for (int k = 0; k < 4; k++){
                    bf16 h0, l0, h1, l1;
                    split2(src[2*k], h0, l0);
                    split2(src[2*k+1], h1, l1);
                    __nv_bfloat162 hp = {h0, h1}, lp = {l0, l1};
                    hw[k] = *(uint32_t*)&hp;
                    lw[k] = *(uint32_t*)&lp;
                }
                *(uint4*)(outH + base) = make_uint4(hw[0], hw[1], hw[2], hw[3]);
                *(uint4*)(outL + base) = make_uint4(lw[0], lw[1], lw[2], lw[3]);
            } else {
                uint32_t hw[4];
                #pragma unroll
                for (int k = 0; k < 4; k++){
                    __half2 hp = {__float2half_rn(src[2*k]), __float2half_rn(src[2*k+1])};
                    hw[k] = *(uint32_t*)&hp;
                }
                *(uint4*)(outH + base) = make_uint4(hw[0], hw[1], hw[2], hw[3]);
            }
        }
        return;
    }
    {
        const int nTot = gridDim.x * 128;
        float* fO = outF; int fm = fmode; int lld = ldc;
        if (dosplit){
            fO = partBase + (size_t)blockIdx.z * Mtot * nTot;
            fm = 1; lld = Mtot;
        }
        #pragma unroll
        for (int i = 0; i < 4; i++){
            const int mA = m0 + wm*64 + i*16 + (lane >> 2);
            const int mB = mA + 8;
            const float bvA = (!dosplit && bias) ? bias[mA]*bScale : 0.f;
            const float bvB = (!dosplit && bias) ? bias[mB]*bScale : 0.f;
            #pragma unroll
            for (int j = 0; j < 4; j++){
                const int nb = n0 + wn*32 + j*8 + (lane & 3)*2;
                float v[4];
                v[0] = acc[i][j][0]*accScale + bvA;  v[1] = acc[i][j][1]*accScale + bvA;
                v[2] = acc[i][j][2]*accScale + bvB;  v[3] = acc[i][j][3]*accScale + bvB;
                if (relu){
                    #pragma unroll
                    for (int r = 0; r < 4; r++) v[r] = fmaxf(v[r], 0.f);
                }
                const int mm[4] = {mA, mA, mB, mB};
                const int nn[4] = {nb, nb + 1, nb, nb + 1};
                #pragma unroll
                for (int r = 0; r < 4; r++){
                    const int m = mm[r], n = nn[r];
                    if (fm == 1)
                        fO[(size_t)n * lld + m] = v[r];
                    else if (fm == 2)
                        fO[(size_t)(n >> 5) * ((size_t)Mtot * 32) + (size_t)m * 32 + (n & 31)] = v[r];
                }
            }
        }
    }
}

// ---------------- transforms ----------------
__global__ __launch_bounds__(256) void wconvb_k(const float* __restrict__ w,
    bf16* __restrict__ h, bf16* __restrict__ l, int O, int C, int isT)
{
    int total = O * C * 3;
    for (int i = blockIdx.x*blockDim.x + threadIdx.x; i < total; i += gridDim.x*blockDim.x){
        int o = i / (C*3), r = i % (C*3), c = r / 3, k = r % 3;
        float v = isT ? w[((size_t)c*O + o)*3 + (2 - k)] : w[i];
        size_t d = (size_t)o*(3*C) + k*C + c;
        bf16 hh, ll; split2(v, hh, ll); h[d] = hh; l[d] = ll;
    }
}
__global__ __launch_bounds__(256) void wconvh_k(const float* __restrict__ w,
    __half* __restrict__ h, __half* __restrict__ l, int O, int C)
{
    int total = O * C * 3;   // always convT source
    for (int i = blockIdx.x*blockDim.x + threadIdx.x; i < total; i += gridDim.x*blockDim.x){
        int o = i / (C*3), r = i % (C*3), c = r / 3, k = r % 3;
        float v = w[((size_t)c*O + o)*3 + (2 - k)];
        size_t d = (size_t)o*(3*C) + k*C + c;
        __half hh, ll; split2h(v, hh, ll); h[d] = hh; l[d] = ll;
    }
}
__global__ __launch_bounds__(256) void wfe_k(const float* __restrict__ w,
    bf16* __restrict__ h, bf16* __restrict__ l)
{
    size_t total = (size_t)512*16384;
    for (size_t i = blockIdx.x*(size_t)blockDim.x + threadIdx.x; i < total;
         i += (size_t)gridDim.x*blockDim.x){
        int e = (int)(i >> 14), fp = (int)(i & 16383);
        int t = fp >> 9, c = fp & 511;
        float v = w[(size_t)e*16384 + c*32 + t];
        bf16 hh, ll; split2(v, hh, ll); h[i] = hh; l[i] = ll;
    }
}
__global__ __launch_bounds__(256) void wfd_k(const float* __restrict__ w,
    __half* __restrict__ h)
{
    size_t total = (size_t)16384*512;
    for (size_t i = blockIdx.x*(size_t)blockDim.x + threadIdx.x; i < total;
         i += (size_t)gridDim.x*blockDim.x){
        int fp = (int)(i >> 9), e = (int)(i & 511);
        int t = fp >> 9, c = fp & 511;
        h[i] = __float2half_rn(w[((size_t)(c*32 + t))*512 + e]);
    }
}
__global__ __launch_bounds__(256) void dfb2_k(const float* __restrict__ b,
    float* __restrict__ b2)
{
    int i = blockIdx.x*blockDim.x + threadIdx.x;
    int t = i >> 9, c = i & 511;
    b2[i] = b[c*32 + t] * QSC;
}
__global__ __launch_bounds__(256) void plainsplit_k(const float* __restrict__ s,
    bf16* __restrict__ h, bf16* __restrict__ l, size_t n)
{
    for (size_t i = blockIdx.x*(size_t)blockDim.x + threadIdx.x; i < n;
         i += (size_t)gridDim.x*blockDim.x){
        bf16 hh, ll; split2(s[i], hh, ll); h[i] = hh; l[i] = ll;
    }
}
__global__ __launch_bounds__(256) void xsplit_k(const float* __restrict__ x,
    bf16* __restrict__ h, bf16* __restrict__ l)
{
    size_t total = (size_t)BB*CIN*TT;
    for (size_t i = blockIdx.x*(size_t)blockDim.x + threadIdx.x; i < total;
         i += (size_t)gridDim.x*blockDim.x){
        int b = (int)(i >> 13), r = (int)(i & 8191);
        int c = r >> 5, t = r & 31;
        size_t d = (size_t)(b*32 + t)*256 + c;
        bf16 hh, ll; split2(x[i], hh, ll); h[d] = hh; l[d] = ll;
    }
}
__global__ __launch_bounds__(256) void reducez_k(const float* __restrict__ part,
    const float* __restrict__ efb, float* __restrict__ z,
    bf16* __restrict__ zh, bf16* __restrict__ zl)
{
    int i = blockIdx.x*blockDim.x + threadIdx.x;
    int e = i & 511;
    float s = 0.f;
    #pragma unroll
    for (int k = 0; k < 8; k++) s += part[(size_t)k*524288 + i];
    s += efb[e];
    z[i] = s;
    bf16 hh, ll; split2(s, hh, ll); zh[i] = hh; zl[i] = ll;
}
__global__ __launch_bounds__(256) void cnorm_k(const float* __restrict__ cb,
                                               float* __restrict__ cn)
{
    int n = blockIdx.x*8 + (threadIdx.x >> 5);
    int lane = threadIdx.x & 31;
    const float* r = cb + (size_t)n*EE;
    float s = 0.f;
    for (int e = lane; e < EE; e += 32){ float v = r[e]; s += v*v; }
    #pragma unroll
    for (int o = 16; o; o >>= 1) s += __shfl_down_sync(0xffffffffu, s, o);
    if (lane == 0) cn[n] = s;
}
__global__ __launch_bounds__(256) void vq_k(
    const float* __restrict__ z, const float* __restrict__ dot,
    const float* __restrict__ cn, const float* __restrict__ cb,
    __half* __restrict__ zqh, __half* __restrict__ zql, float* __restrict__ lp)
{
    __shared__ float sv[256];
    __shared__ int   si[256];
    __shared__ float s_zn;
    const int b = blockIdx.x, tid = threadIdx.x;
    const float* zb = z + (size_t)b*EE;

    float zn = 0.f;
    for (int e = tid; e < EE; e += 256){ float v = zb[e]; zn += v*v; }
    sv[tid] = zn; __syncthreads();
    for (int s = 128; s > 0; s >>= 1){ if (tid < s) sv[tid] += sv[tid+s]; __syncthreads(); }
    if (tid == 0) s_zn = sv[0];
    __syncthreads();
    zn = s_zn; __syncthreads();

    const float* db = dot + (size_t)b*NEC;
    float best = 3.4e38f; int bi = 0x7fffffff;
    for (int n = tid; n < NEC; n += 256){
        float dv = (zn + cn[n]) - 2.0f * db[n];
        if (dv < best || (dv == best && n < bi)){ best = dv; bi = n; }
    }
    sv[tid] = best; si[tid] = bi; __syncthreads();
    for (int s = 128; s > 0; s >>= 1){
        if (tid < s){
            float v2 = sv[tid+s]; int i2 = si[tid+s];
            if (v2 < sv[tid] || (v2 == sv[tid] && i2 < si[tid])){ sv[tid] = v2; si[tid] = i2; }
        }
        __syncthreads();
    }
    const int idx = si[0];
    __syncthreads();

    const float* cbr = cb + (size_t)idx*EE;
    float ls = 0.f;
    for (int e = tid; e < EE; e += 256){
        float q = cbr[e];
        __half hh, ll; split2h(q*QSC, hh, ll);
        zqh[(size_t)b*EE + e] = hh; zql[(size_t)b*EE + e] = ll;
        float d = q - zb[e]; ls += d*d;
    }
    sv[tid] = ls; __syncthreads();
    for (int s = 128; s > 0; s >>= 1){ if (tid < s) sv[tid] += sv[tid+s]; __syncthreads(); }
    if (tid == 0) lp[b] = sv[0];
}
__global__ __launch_bounds__(256) void loss_final_k(const float* __restrict__ lp,
                                                    float* __restrict__ outLoss)
{
    __shared__ float sm[256];
    int tid = threadIdx.x;
    float s = 0.f;
    #pragma unroll
    for (int i = 0; i < 4; i++) s += lp[tid + i*256];
    sm[tid] = s; __syncthreads();
    for (int st = 128; st > 0; st >>= 1){ if (tid < st) sm[tid] += sm[tid+st]; __syncthreads(); }
    if (tid == 0) *outLoss = sm[0] * 1.25f / ((float)BB * (float)EE);
}

// =====================================================================
#define SYM(p, s) do{ void* _t; cudaGetSymbolAddress(&_t, s); p = (decltype(p))_t; }while(0)
#define U16(p) ((uint16_t*)(p))

extern "C" void kernel_launch(void* const* d_in, const int* in_sizes, int n_in,
                              void* d_out, int out_size)
{
    const float* x   = (const float*)d_in[0];
    const float* ew1 = (const float*)d_in[1];  const float* eb1 = (const float*)d_in[2];
    const float* ew2 = (const float*)d_in[3];  const float* eb2 = (const float*)d_in[4];
    const float* ew3 = (const float*)d_in[5];  const float* eb3 = (const float*)d_in[6];
    const float* ew4 = (const float*)d_in[7];  const float* eb4 = (const float*)d_in[8];
    const float* efw = (const float*)d_in[9];  const float* efb = (const float*)d_in[10];
    const float* cb  = (const float*)d_in[11];
    const float* dfw = (const float*)d_in[12]; const float* dfb = (const float*)d_in[13];
    const float* dw4 = (const float*)d_in[14]; const float* db4 = (const float*)d_in[15];
    const float* dw3 = (const float*)d_in[16]; const float* db3 = (const float*)d_in[17];
    const float* dw2 = (const float*)d_in[18]; const float* db2 = (const float*)d_in[19];
    const float* dw1 = (const float*)d_in[20]; const float* db1 = (const float*)d_in[21];
    float* out = (float*)d_out;

    bf16 *aAh,*aAl,*aBh,*aBl;
    bf16 *w1h,*w1l,*w2h,*w2l,*w3h,*w3l,*w4h,*w4l;
    __half *d4h,*d4l,*d3h,*d3l,*d2h,*d2l,*d1h,*d1l,*fd,*zqh,*zql;
    bf16 *feh,*fel,*cbh,*cbl,*zh,*zl;
    float *part,*z,*dot,*cn,*lp,*dfb2;
    SYM(aAh,g_actAh); SYM(aAl,g_actAl); SYM(aBh,g_actBh); SYM(aBl,g_actBl);
    SYM(w1h,g_wA1h); SYM(w1l,g_wA1l); SYM(w2h,g_wA2h); SYM(w2l,g_wA2l);
    SYM(w3h,g_wA3h); SYM(w3l,g_wA3l); SYM(w4h,g_wA4h); SYM(w4l,g_wA4l);
    SYM(d4h,g_wD4h); SYM(d4l,g_wD4l); SYM(d3h,g_wD3h); SYM(d3l,g_wD3l);
    SYM(d2h,g_wD2h); SYM(d2l,g_wD2l); SYM(d1h,g_wD1h); SYM(d1l,g_wD1l);
    SYM(feh,g_wFEh); SYM(fel,g_wFEl); SYM(fd,g_wFD);
    SYM(cbh,g_cbh);  SYM(cbl,g_cbl);
    SYM(zh,g_zh); SYM(zl,g_zl); SYM(zqh,g_zqh); SYM(zql,g_zql);
    SYM(part,g_part); SYM(z,g_z); SYM(dot,g_dot); SYM(cn,g_cn); SYM(lp,g_lp);
    SYM(dfb2,g_dfb2);

    cudaFuncSetAttribute(gemm_mma<0>, cudaFuncAttributeMaxDynamicSharedMemorySize, GS);
    cudaFuncSetAttribute(gemm_mma<1>, cudaFuncAttributeMaxDynamicSharedMemorySize, GS);
    cudaFuncSetAttribute(gemm_mma<2>, cudaFuncAttributeMaxDynamicSharedMemorySize, GS);

    // launches 1-5, then gemm as #6 (ncu -s 5 capture)
    xsplit_k<<<1024, 256>>>(x, aAh, aAl);
    wconvb_k<<<512, 256>>>(ew1, w1h, w1l, 512, 256, 0);
    wconvb_k<<<512, 256>>>(ew2, w2h, w2l, 512, 512, 0);
    wconvb_k<<<512, 256>>>(ew3, w3h, w3l, 512, 512, 0);
    wconvb_k<<<512, 256>>>(ew4, w4h, w4l, 512, 512, 0);

    // ---- encoder convs (MODE 0, bf16 3-term) ----
    gemm_mma<0><<<dim3(NNC/128, 4, 1), 256, GS>>>(U16(w1h), U16(w1l), U16(aAh), U16(aAl),
        eb1, nullptr, U16(aBh), U16(aBl), nullptr, 512, 768,  768,  256, 0, 0, 1, 1.f, 1.f);
    gemm_mma<0><<<dim3(NNC/128, 4, 1), 256, GS>>>(U16(w2h), U16(w2l), U16(aBh), U16(aBl),
        eb2, nullptr, U16(aAh), U16(aAl), nullptr, 512, 1536, 1536, 512, 0, 0, 1, 1.f, 1.f);
    gemm_mma<0><<<dim3(NNC/128, 4, 1), 256, GS>>>(U16(w3h), U16(w3l), U16(aAh), U16(aAl),
        eb3, nullptr, U16(aBh), U16(aBl), nullptr, 512, 1536, 1536, 512, 0, 0, 1, 1.f, 1.f);
    gemm_mma<0><<<dim3(NNC/128, 4, 1), 256, GS>>>(U16(w4h), U16(w4l), U16(aBh), U16(aBl),
        eb4, nullptr, U16(aAh), U16(aAl), nullptr, 512, 1536, 1536, 512, 0, 0, 1, 1.f, 1.f);

    // ---- remaining transforms ----
    wfe_k<<<2048, 256>>>(efw, feh, fel);
    plainsplit_k<<<2048, 256>>>(cb, cbh, cbl, (size_t)NEC*EE);
    cnorm_k<<<NEC/8, 256>>>(cb, cn);
    wfd_k<<<2048, 256>>>(dfw, fd);
    dfb2_k<<<64, 256>>>(dfb, dfb2);
    wconvh_k<<<512, 256>>>(dw4, d4h, d4l, 512, 512);
    wconvh_k<<<512, 256>>>(dw3, d3h, d3l, 512, 512);
    wconvh_k<<<512, 256>>>(dw2, d2h, d2l, 512, 512);
    wconvh_k<<<512, 256>>>(dw1, d1h, d1l, 256, 512);

    // ---- encoder FC: split-K=8, MODE 0 ----
    gemm_mma<0><<<dim3(BB/128, 4, 8), 256, GS>>>(U16(feh), U16(fel), U16(aAh), U16(aAl),
        nullptr, nullptr, nullptr, nullptr, part, 512, 16384, 2048, 0, 0, 0, 0, 1.f, 1.f);
    reducez_k<<<2048, 256>>>(part, efb, z, zh, zl);

    // ---- VQ dot (MODE 0) ----
    gemm_mma<0><<<dim3(BB/128, NEC/128, 1), 256, GS>>>(U16(cbh), U16(cbl), U16(zh), U16(zl),
        nullptr, dot, nullptr, nullptr, nullptr, NEC, EE, EE, 0, 1, NEC, 0, 1.f, 1.f);
    vq_k<<<BB, 256>>>(z, dot, cn, cb, zqh, zql, lp);

    // ---- decoder FC (MODE 2: zq*QSC exact pair, dfw single fp16) ----
    // acc already scaled by QSC via zq; bias pre-scaled; act stays scaled.
    gemm_mma<2><<<dim3(BB/128, 16384/128, 1), 256, GS>>>(U16(fd), nullptr, U16(zqh), U16(zql),
        dfb2, nullptr, U16(aBh), nullptr, nullptr, 16384, EE, EE, 0, 0, 0, 0, 1.f, 1.f);

    // ---- decoder convs (MODE 1: weight pair, act single fp16, scaled domain) ----
    gemm_mma<1><<<dim3(NNC/128, 4, 1), 256, GS>>>(U16(d4h), U16(d4l), U16(aBh), nullptr,
        db4, nullptr, U16(aAh), nullptr, nullptr, 512, 1536, 1536, 512, 0, 0, 1, 1.f, QSC);
    gemm_mma<1><<<dim3(NNC/128, 4, 1), 256, GS>>>(U16(d3h), U16(d3l), U16(aAh), nullptr,
        db3, nullptr, U16(aBh), nullptr, nullptr, 512, 1536, 1536, 512, 0, 0, 1, 1.f, QSC);
    gemm_mma<1><<<dim3(NNC/128, 4, 1), 256, GS>>>(U16(d2h), U16(d2l), U16(aBh), nullptr,
        db2, nullptr, U16(aAh), nullptr, nullptr, 512, 1536, 1536, 512, 0, 0, 1, 1.f, QSC);
    // final conv: descale recon
    gemm_mma<1><<<dim3(NNC/128, 2, 1), 256, GS>>>(U16(d1h), U16(d1l), U16(aAh), nullptr,
        db1, out, nullptr, nullptr, nullptr, 256, 1536, 1536, 512, 2, 0, 0, 1.0f/QSC, 1.f);

    if (out_size >= RECON_N + 1)
        loss_final_k<<<1, 256>>>(lp, out + RECON_N);
}